// round 7
// baseline (speedup 1.0000x reference)
#include <cuda_runtime.h>
#include <cuda_bf16.h>
#include <math.h>
#include <stdint.h>

// Problem constants
#define B_   64
#define T_   2048
#define E_   512
#define R_   1024
#define A_   128
#define F_   32
#define KW   31
#define PADW 15
#define KIM  62
#define KTOT 576
#define KC2  64          // original-K per chunk
#define NCK  9           // 576/64
#define TM   128         // t rows per block
#define NPART 16         // T_/TM

typedef unsigned long long u64;

// Scratch (device globals; no allocations allowed)
__device__ float g_pq[B_ * A_];
__device__ __align__(16) __nv_bfloat16 g_Whi[A_ * KTOT];  // W^T hi split: [a][k]
__device__ __align__(16) __nv_bfloat16 g_Wlo[A_ * KTOT];  // W^T lo split
__device__ float g_align[B_ * T_];
__device__ float g_part[NPART * B_ * E_];

// ---- dynamic smem layout ----
#define OFF_AHI 0
#define OFF_ALO 16384
#define OFF_BHI 32768
#define OFF_BLO 49152
#define OFF_STG 65536            // 32 KB raw fp32 A staging (thread-private slots)
#define OFF_PQ  (OFF_STG + 32768)
#define OFF_V   (OFF_PQ + 512)
#define OFF_AL  (OFF_V + 512)
#define OFF_EN  (OFF_AL + 512)
#define SMEM_SZ (OFF_EN + 2048)  // 101888 B -> 2 CTAs/SM

__device__ __forceinline__ uint32_t smem_u32(const void* p) {
    uint32_t a;
    asm("{ .reg .u64 t; cvta.to.shared.u64 t, %1; cvt.u32.u64 %0, t; }" : "=r"(a) : "l"(p));
    return a;
}
// accurate tanh: 1 - 2/(e^{2x}+1) via ex2.approx + rcp.approx (~1e-6 rel)
__device__ __forceinline__ float tanh_fast(float x) {
    float e;
    asm("ex2.approx.f32 %0, %1;" : "=f"(e) : "f"(x * 2.885390081777927f));
    float r;
    asm("rcp.approx.f32 %0, %1;" : "=f"(r) : "f"(e + 1.0f));
    return fmaf(-2.0f, r, 1.0f);
}
__device__ __forceinline__ void ldsm4(uint32_t addr, uint32_t& r0, uint32_t& r1,
                                      uint32_t& r2, uint32_t& r3) {
    asm volatile("ldmatrix.sync.aligned.m8n8.x4.shared.b16 {%0,%1,%2,%3}, [%4];"
                 : "=r"(r0), "=r"(r1), "=r"(r2), "=r"(r3) : "r"(addr));
}
__device__ __forceinline__ void mma16816(float* c, const uint32_t* a, uint32_t b0, uint32_t b1) {
    asm volatile(
        "mma.sync.aligned.m16n8k16.row.col.f32.bf16.bf16.f32 "
        "{%0,%1,%2,%3}, {%4,%5,%6,%7}, {%8,%9}, {%0,%1,%2,%3};"
        : "+f"(c[0]), "+f"(c[1]), "+f"(c[2]), "+f"(c[3])
        : "r"(a[0]), "r"(a[1]), "r"(a[2]), "r"(a[3]), "r"(b0), "r"(b1));
}
__device__ __forceinline__ uint32_t cvt_bf2(float hi_elem, float lo_elem) {
    uint32_t r;
    asm("cvt.rn.bf16x2.f32 %0, %1, %2;" : "=r"(r) : "f"(hi_elem), "f"(lo_elem));
    return r;
}
__device__ __forceinline__ void cp_async16(uint32_t dst, const void* src) {
    asm volatile("cp.async.ca.shared.global [%0], [%1], 16;" :: "r"(dst), "l"(src));
}
__device__ __forceinline__ void cp_commit() {
    asm volatile("cp.async.commit_group;" ::: "memory");
}
__device__ __forceinline__ void cp_wait_all() {
    asm volatile("cp.async.wait_group 0;" ::: "memory");
}

// ---------------- pq = attention_hidden @ W_query : (B, A) ----------------
__global__ void k_pq(const float* __restrict__ hid, const float* __restrict__ Wq) {
    __shared__ float sh[R_];
    int b = blockIdx.x, tid = threadIdx.x;
    for (int i = tid; i < R_; i += 128) sh[i] = hid[b * R_ + i];
    __syncthreads();
    float acc = 0.f;
#pragma unroll 8
    for (int r = 0; r < R_; r++) acc += sh[r] * Wq[r * A_ + tid];
    g_pq[b * A_ + tid] = acc;
}

// ---- Wcat^T bf16 split: k<512 = W_memory, 512..573 = conv.W_loc, rest 0 ----
__global__ void k_wcat(const float* __restrict__ Wm, const float* __restrict__ cw,
                       const float* __restrict__ Wl) {
    int row = blockIdx.x;  // k: 0..575
    int a = threadIdx.x;   // 0..127
    float v = 0.f;
    if (row < E_) {
        v = Wm[row * A_ + a];
    } else if (row < E_ + KIM) {
        int ck = row - E_;
        int c = ck / KW, k = ck - c * KW;
#pragma unroll
        for (int f = 0; f < F_; f++)
            v += cw[f * (2 * KW) + c * KW + k] * Wl[f * A_ + a];
    }
    __nv_bfloat16 h = __float2bfloat16_rn(v);
    float lo = v - __bfloat162float(h);
    g_Whi[a * KTOT + row] = h;
    g_Wlo[a * KTOT + row] = __float2bfloat16_rn(lo);
}

// ---------------- main: mma.sync bf16 3-split GEMM, cp.async pipelined ----------------
__global__ void __launch_bounds__(256, 2)
k_main(const float* __restrict__ mem, const float* __restrict__ aw,
       const int* __restrict__ mask, const float* __restrict__ vw,
       const float* __restrict__ vb) {
    extern __shared__ char smc[];
    uint32_t sb = smem_u32(smc);
    int tid = threadIdx.x;
    int l = tid & 31, w = tid >> 5;
    int wa = w & 3, wt = w >> 2;      // warp tile: 64t (wt) x 32a (wa)
    int b = blockIdx.y, tb = blockIdx.x * TM;

    if (tid < A_) {
        ((float*)(smc + OFF_PQ))[tid] = g_pq[b * A_ + tid];
        ((float*)(smc + OFF_V))[tid]  = vw[tid];
    }

    float acc[4][4][4];
#pragma unroll
    for (int i = 0; i < 4; i++)
#pragma unroll
        for (int j = 0; j < 4; j++)
#pragma unroll
            for (int k = 0; k < 4; k++) acc[i][j][k] = 0.f;

    const float* memB = mem + ((size_t)b * T_ + tb) * E_;
    const float* awB  = aw + (size_t)b * 2 * T_;

    // conversion mapping: 256 threads -> 128 rows x 2 k-halves of 32
    int crow = tid >> 1, chalf = (tid & 1) * 32;
    uint32_t cRowBase = (uint32_t)crow * 128u;
    int cSwz = crow & 7;
    uint32_t stgBase = sb + OFF_STG + (uint32_t)tid * 16u;   // + q*4096
    const float* aSrcBase = memB + (size_t)crow * E_ + chalf; // + c*64 + q*4

    // ldmatrix lane constants
    int rowA = wt * 64 + (l & 15);
    uint32_t aRowBase = (uint32_t)rowA * 128u;
    int aSwz = rowA & 7;
    int kpA = (l >> 4) & 1;
    int nB = wa * 32 + ((l & 16) >> 1) + (l & 7);
    uint32_t bRowBase = (uint32_t)nB * 128u;
    int bSwz = l & 7;
    int kpB = (l >> 3) & 1;

    // prologue: prefetch raw A chunk 0 into stage
#pragma unroll
    for (int q = 0; q < 8; q++)
        cp_async16(stgBase + (uint32_t)q * 4096u, aSrcBase + q * 4);
    cp_commit();

#pragma unroll 1
    for (int c = 0; c < NCK; c++) {
        __syncthreads();   // previous compute done before tile overwrite

        // ---- B copy: 128 a-rows x 64 k, hi/lo, swizzled (L2-hot) ----
#pragma unroll
        for (int i = 0; i < 4; i++) {
            int idx = i * 256 + tid;
            int n = idx >> 3, q = idx & 7;
            uint32_t off = (uint32_t)n * 128u + (uint32_t)(((q ^ (n & 7)) << 4));
            const char* sh = (const char*)g_Whi + (size_t)n * (KTOT * 2) + c * 128 + q * 16;
            const char* sl = (const char*)g_Wlo + (size_t)n * (KTOT * 2) + c * 128 + q * 16;
            *(uint4*)(smc + OFF_BHI + off) = *(const uint4*)sh;
            *(uint4*)(smc + OFF_BLO + off) = *(const uint4*)sl;
        }

        // ---- A convert: 32 fp32 -> bf16 hi/lo, swizzled STS ----
        if (c < 8) {
            cp_wait_all();   // stage for chunk c ready (thread-private slots)
#pragma unroll
            for (int u = 0; u < 4; u++) {       // 2 stage units (8 floats) per u
                float4 v0 = *(const float4*)(smc + OFF_STG + (2 * u) * 4096 + tid * 16);
                float4 v1 = *(const float4*)(smc + OFF_STG + (2 * u + 1) * 4096 + tid * 16);
                float xs[8] = {v0.x, v0.y, v0.z, v0.w, v1.x, v1.y, v1.z, v1.w};
                uint32_t hw[4], lw[4];
#pragma unroll
                for (int p = 0; p < 4; p++) {
                    float x0 = xs[2 * p], x1 = xs[2 * p + 1];
                    uint32_t h = cvt_bf2(x1, x0);
                    float f0 = __uint_as_float(h << 16);
                    float f1 = __uint_as_float(h & 0xffff0000u);
                    lw[p] = cvt_bf2(x1 - f1, x0 - f0);
                    hw[p] = h;
                }
                int q = (chalf >> 3) + u;
                uint32_t off = cRowBase + (uint32_t)((q ^ cSwz) << 4);
                *(uint4*)(smc + OFF_AHI + off) = make_uint4(hw[0], hw[1], hw[2], hw[3]);
                *(uint4*)(smc + OFF_ALO + off) = make_uint4(lw[0], lw[1], lw[2], lw[3]);
            }
        } else {
            // im2col chunk (direct path)
#pragma unroll
            for (int u = 0; u < 4; u++) {
                float xs[8];
#pragma unroll
                for (int j = 0; j < 8; j++) {
                    int kk = chalf + u * 8 + j;
                    float v = 0.f;
                    if (kk < KIM) {
                        int ci = (kk >= KW) ? 1 : 0;
                        int kp = kk - ci * KW;
                        int tg = tb + crow + kp - PADW;
                        if (tg >= 0 && tg < T_) v = awB[ci * T_ + tg];
                    }
                    xs[j] = v;
                }
                uint32_t hw[4], lw[4];
#pragma unroll
                for (int p = 0; p < 4; p++) {
                    float x0 = xs[2 * p], x1 = xs[2 * p + 1];
                    uint32_t h = cvt_bf2(x1, x0);
                    float f0 = __uint_as_float(h << 16);
                    float f1 = __uint_as_float(h & 0xffff0000u);
                    lw[p] = cvt_bf2(x1 - f1, x0 - f0);
                    hw[p] = h;
                }
                int q = (chalf >> 3) + u;
                uint32_t off = cRowBase + (uint32_t)((q ^ cSwz) << 4);
                *(uint4*)(smc + OFF_AHI + off) = make_uint4(hw[0], hw[1], hw[2], hw[3]);
                *(uint4*)(smc + OFF_ALO + off) = make_uint4(lw[0], lw[1], lw[2], lw[3]);
            }
        }
        __syncthreads();

        // ---- prefetch raw A for chunk c+1 during compute ----
        if (c + 1 < 8) {
            const float* src = aSrcBase + (c + 1) * KC2;
#pragma unroll
            for (int q = 0; q < 8; q++)
                cp_async16(stgBase + (uint32_t)q * 4096u, src + q * 4);
            cp_commit();
        }

        // ---- merged compute: Ahi*Bhi + Ahi*Blo + Alo*Bhi ----
#pragma unroll
        for (int s = 0; s < 4; s++) {
            uint32_t bh[8], bl[8];
            uint32_t kbB = (uint32_t)((((2 * s + kpB) ^ bSwz) << 4));
            ldsm4(sb + OFF_BHI + bRowBase + kbB,          bh[0], bh[1], bh[2], bh[3]);
            ldsm4(sb + OFF_BHI + bRowBase + 2048u + kbB,  bh[4], bh[5], bh[6], bh[7]);
            ldsm4(sb + OFF_BLO + bRowBase + kbB,          bl[0], bl[1], bl[2], bl[3]);
            ldsm4(sb + OFF_BLO + bRowBase + 2048u + kbB,  bl[4], bl[5], bl[6], bl[7]);
            uint32_t kbA = (uint32_t)((((2 * s + kpA) ^ aSwz) << 4));
#pragma unroll
            for (int mi = 0; mi < 4; mi++) {
                uint32_t ah[4], al[4];
                ldsm4(sb + OFF_AHI + aRowBase + mi * 2048u + kbA, ah[0], ah[1], ah[2], ah[3]);
                ldsm4(sb + OFF_ALO + aRowBase + mi * 2048u + kbA, al[0], al[1], al[2], al[3]);
                mma16816(acc[mi][0], ah, bh[0], bh[1]);
                mma16816(acc[mi][1], ah, bh[2], bh[3]);
                mma16816(acc[mi][2], ah, bh[4], bh[5]);
                mma16816(acc[mi][3], ah, bh[6], bh[7]);
                mma16816(acc[mi][0], ah, bl[0], bl[1]);
                mma16816(acc[mi][1], ah, bl[2], bl[3]);
                mma16816(acc[mi][2], ah, bl[4], bl[5]);
                mma16816(acc[mi][3], ah, bl[6], bl[7]);
                mma16816(acc[mi][0], al, bh[0], bh[1]);
                mma16816(acc[mi][1], al, bh[2], bh[3]);
                mma16816(acc[mi][2], al, bh[4], bh[5]);
                mma16816(acc[mi][3], al, bh[6], bh[7]);
            }
        }
    }

    // ---- epilogue: en[t] = sum_a v[a] * tanh(D[t,a] + pq[a]) ----
    {
        const float* sPQ = (const float*)(smc + OFF_PQ);
        const float* sV  = (const float*)(smc + OFF_V);
        float* sEn = (float*)(smc + OFF_EN);   // [4 wa][128 t]
#pragma unroll
        for (int mi = 0; mi < 4; mi++) {
            float en1 = 0.f, en2 = 0.f;
#pragma unroll
            for (int nj = 0; nj < 4; nj++) {
                int a0 = wa * 32 + nj * 8 + 2 * (l & 3);
                float v0 = sV[a0], v1 = sV[a0 + 1];
                float q0 = sPQ[a0], q1 = sPQ[a0 + 1];
                en1 += v0 * tanh_fast(acc[mi][nj][0] + q0) + v1 * tanh_fast(acc[mi][nj][1] + q1);
                en2 += v0 * tanh_fast(acc[mi][nj][2] + q0) + v1 * tanh_fast(acc[mi][nj][3] + q1);
            }
            en1 += __shfl_xor_sync(0xffffffffu, en1, 1);
            en1 += __shfl_xor_sync(0xffffffffu, en1, 2);
            en2 += __shfl_xor_sync(0xffffffffu, en2, 1);
            en2 += __shfl_xor_sync(0xffffffffu, en2, 2);
            if ((l & 3) == 0) {
                int r1 = wt * 64 + mi * 16 + (l >> 2);
                sEn[wa * TM + r1] = en1;
                sEn[wa * TM + r1 + 8] = en2;
            }
        }
    }
    __syncthreads();
    if (tid < TM) {
        float* sEn = (float*)(smc + OFF_EN);
        float al = sEn[tid] + sEn[TM + tid] + sEn[2 * TM + tid] + sEn[3 * TM + tid] + vb[0];
        if (mask[b * T_ + tb + tid]) al += -1e25f;
        g_align[b * T_ + tb + tid] = al;
        ((float*)(smc + OFF_AL))[tid] = al;
    }
    __syncthreads();

    // ---- fused output GEMV partials: part[e] = sum_t align[t] * mem[b,tb+t,e] ----
    {
        const float* sAl = (const float*)(smc + OFF_AL);
        int e2 = tid * 2;
        float a0 = 0.f, a1 = 0.f;
        const float* mp = memB + e2;
#pragma unroll 8
        for (int t = 0; t < TM; t++) {
            float al = sAl[t];
            float2 m = *(const float2*)(mp + (size_t)t * E_);
            a0 = fmaf(al, m.x, a0);
            a1 = fmaf(al, m.y, a1);
        }
        float2 res; res.x = a0; res.y = a1;
        *(float2*)(g_part + (size_t)blockIdx.x * (B_ * E_) + b * E_ + e2) = res;
    }
}

// ---------------- softmax over T per batch -> attention_weights ----------------
__global__ void k_softmax(float* __restrict__ outw) {
    __shared__ float sE[T_];
    __shared__ float red[256];
    int b = blockIdx.x, tid = threadIdx.x;
    float mx = -3.4e38f;
    for (int i = tid; i < T_; i += 256) {
        float v = g_align[b * T_ + i];
        sE[i] = v;
        mx = fmaxf(mx, v);
    }
    red[tid] = mx;
    __syncthreads();
    for (int s = 128; s > 0; s >>= 1) {
        if (tid < s) red[tid] = fmaxf(red[tid], red[tid + s]);
        __syncthreads();
    }
    mx = red[0];
    __syncthreads();
    float sum = 0.f;
    for (int i = tid; i < T_; i += 256) {
        float ev = expf(sE[i] - mx);
        sE[i] = ev;
        sum += ev;
    }
    red[tid] = sum;
    __syncthreads();
    for (int s = 128; s > 0; s >>= 1) {
        if (tid < s) red[tid] += red[tid + s];
        __syncthreads();
    }
    float inv = 1.f / red[0];
    for (int i = tid; i < T_; i += 256) outw[b * T_ + i] = sE[i] * inv;
}

// ---------------- reduce GEMV partials ----------------
__global__ void k_reduce(float* __restrict__ outa) {
    int b = blockIdx.x, e = threadIdx.x;
    float s = 0.f;
#pragma unroll
    for (int p = 0; p < NPART; p++) s += g_part[(size_t)p * (B_ * E_) + b * E_ + e];
    outa[b * E_ + e] = s;
}

// ---------------- launch ----------------
extern "C" void kernel_launch(void* const* d_in, const int* in_sizes, int n_in,
                              void* d_out, int out_size) {
    (void)in_sizes; (void)n_in; (void)out_size;
    const float* hid  = (const float*)d_in[0];  // (B, R)
    const float* mem  = (const float*)d_in[1];  // (B, T, E)
    const float* aw   = (const float*)d_in[2];  // (B, 2, T)
    const int*   mask = (const int*)d_in[3];    // (B, T)
    const float* Wq   = (const float*)d_in[4];  // (R, A)
    const float* Wm   = (const float*)d_in[5];  // (E, A)
    const float* cw   = (const float*)d_in[6];  // (F, 2, K)
    const float* Wl   = (const float*)d_in[7];  // (F, A)
    const float* vw   = (const float*)d_in[8];  // (A,)
    const float* vb   = (const float*)d_in[9];  // (1,)

    float* out      = (float*)d_out;
    float* out_attn = out;              // (B, E)
    float* out_w    = out + B_ * E_;    // (B, T)

    static int configured = 0;
    if (!configured) {
        cudaFuncSetAttribute(k_main, cudaFuncAttributeMaxDynamicSharedMemorySize, SMEM_SZ);
        configured = 1;
    }

    k_pq<<<B_, 128>>>(hid, Wq);
    k_wcat<<<KTOT, 128>>>(Wm, cw, Wl);
    dim3 gm(T_ / TM, B_);
    k_main<<<gm, 256, SMEM_SZ>>>(mem, aw, mask, vw, vb);
    k_softmax<<<B_, 256>>>(out_w);
    k_reduce<<<B_, E_>>>(out_attn);
}

// round 8
// speedup vs baseline: 1.4502x; 1.4502x over previous
#include <cuda_runtime.h>
#include <cuda_bf16.h>
#include <math.h>
#include <stdint.h>

// Problem constants
#define B_   64
#define T_   2048
#define E_   512
#define R_   1024
#define A_   128
#define F_   32
#define KW   31
#define PADW 15
#define KIM  62
#define KTOT 576
#define KC2  64          // original-K per chunk
#define NCK  9           // 576/64
#define TM   128         // t rows per block
#define NPART 16         // T_/TM

typedef unsigned long long u64;

// Scratch (device globals; no allocations allowed)
__device__ float g_pq[B_ * A_];
__device__ __align__(16) __nv_bfloat16 g_Whi[A_ * KTOT];  // W^T hi split: [a][k]
__device__ __align__(16) __nv_bfloat16 g_Wlo[A_ * KTOT];  // W^T lo split
__device__ float g_align[B_ * T_];
__device__ float g_part[NPART * B_ * E_];

// ---- dynamic smem layout: double-buffered A (hi+lo), single B ----
#define OFF_A0H 0
#define OFF_A0L 16384
#define OFF_A1H 32768
#define OFF_A1L 49152
#define OFF_BHI 65536
#define OFF_BLO 81920
#define OFF_PQ  98304
#define OFF_V   98816
#define OFF_AL  99328
#define OFF_EN  99840            // 4 x 128 x 4B
#define SMEM_SZ 101888           // x2 CTA = 203776 <= 228KB

__device__ __forceinline__ uint32_t smem_u32(const void* p) {
    uint32_t a;
    asm("{ .reg .u64 t; cvta.to.shared.u64 t, %1; cvt.u32.u64 %0, t; }" : "=r"(a) : "l"(p));
    return a;
}
// accurate tanh: 1 - 2/(e^{2x}+1) via ex2.approx + rcp.approx (~1e-6 rel)
__device__ __forceinline__ float tanh_fast(float x) {
    float e;
    asm("ex2.approx.f32 %0, %1;" : "=f"(e) : "f"(x * 2.885390081777927f));
    float r;
    asm("rcp.approx.f32 %0, %1;" : "=f"(r) : "f"(e + 1.0f));
    return fmaf(-2.0f, r, 1.0f);
}
__device__ __forceinline__ void ldsm4(uint32_t addr, uint32_t& r0, uint32_t& r1,
                                      uint32_t& r2, uint32_t& r3) {
    asm volatile("ldmatrix.sync.aligned.m8n8.x4.shared.b16 {%0,%1,%2,%3}, [%4];"
                 : "=r"(r0), "=r"(r1), "=r"(r2), "=r"(r3) : "r"(addr));
}
__device__ __forceinline__ void mma16816(float* c, const uint32_t* a, uint32_t b0, uint32_t b1) {
    asm volatile(
        "mma.sync.aligned.m16n8k16.row.col.f32.bf16.bf16.f32 "
        "{%0,%1,%2,%3}, {%4,%5,%6,%7}, {%8,%9}, {%0,%1,%2,%3};"
        : "+f"(c[0]), "+f"(c[1]), "+f"(c[2]), "+f"(c[3])
        : "r"(a[0]), "r"(a[1]), "r"(a[2]), "r"(a[3]), "r"(b0), "r"(b1));
}
__device__ __forceinline__ uint32_t cvt_bf2(float hi_elem, float lo_elem) {
    uint32_t r;
    asm("cvt.rn.bf16x2.f32 %0, %1, %2;" : "=r"(r) : "f"(hi_elem), "f"(lo_elem));
    return r;
}

// ---------------- pq = attention_hidden @ W_query : (B, A) ----------------
__global__ void k_pq(const float* __restrict__ hid, const float* __restrict__ Wq) {
    __shared__ float sh[R_];
    int b = blockIdx.x, tid = threadIdx.x;
    for (int i = tid; i < R_; i += 128) sh[i] = hid[b * R_ + i];
    __syncthreads();
    float acc = 0.f;
#pragma unroll 8
    for (int r = 0; r < R_; r++) acc += sh[r] * Wq[r * A_ + tid];
    g_pq[b * A_ + tid] = acc;
}

// ---- Wcat^T bf16 split: k<512 = W_memory, 512..573 = conv.W_loc, rest 0 ----
__global__ void k_wcat(const float* __restrict__ Wm, const float* __restrict__ cw,
                       const float* __restrict__ Wl) {
    int row = blockIdx.x;  // k: 0..575
    int a = threadIdx.x;   // 0..127
    float v = 0.f;
    if (row < E_) {
        v = Wm[row * A_ + a];
    } else if (row < E_ + KIM) {
        int ck = row - E_;
        int c = ck / KW, k = ck - c * KW;
#pragma unroll
        for (int f = 0; f < F_; f++)
            v += cw[f * (2 * KW) + c * KW + k] * Wl[f * A_ + a];
    }
    __nv_bfloat16 h = __float2bfloat16_rn(v);
    float lo = v - __bfloat162float(h);
    g_Whi[a * KTOT + row] = h;
    g_Wlo[a * KTOT + row] = __float2bfloat16_rn(lo);
}

// ---------------- main: mma.sync bf16 3-split, convert overlapped with MMA ----------------
__global__ void __launch_bounds__(256, 2)
k_main(const float* __restrict__ mem, const float* __restrict__ aw,
       const int* __restrict__ mask, const float* __restrict__ vw,
       const float* __restrict__ vb) {
    extern __shared__ char smc[];
    uint32_t sb = smem_u32(smc);
    int tid = threadIdx.x;
    int l = tid & 31, w = tid >> 5;
    int wa = w & 3, wt = w >> 2;      // warp tile: 64t (wt) x 32a (wa)
    int b = blockIdx.y, tb = blockIdx.x * TM;

    if (tid < A_) {
        ((float*)(smc + OFF_PQ))[tid] = g_pq[b * A_ + tid];
        ((float*)(smc + OFF_V))[tid]  = vw[tid];
    }

    float acc[4][4][4];
#pragma unroll
    for (int i = 0; i < 4; i++)
#pragma unroll
        for (int j = 0; j < 4; j++)
#pragma unroll
            for (int k = 0; k < 4; k++) acc[i][j][k] = 0.f;

    const float* memB = mem + ((size_t)b * T_ + tb) * E_;
    const float* awB  = aw + (size_t)b * 2 * T_;

    // conversion mapping: 256 threads -> 128 rows x 2 k-halves of 32
    int crow = tid >> 1, chalf = (tid & 1) * 32;
    uint32_t cRowBase = (uint32_t)crow * 128u;
    int cSwz = crow & 7;
    const float* aCvtBase = memB + (size_t)crow * E_ + chalf;

    // ldmatrix lane constants
    int rowA = wt * 64 + (l & 15);
    uint32_t aRowBase = (uint32_t)rowA * 128u;
    int aSwz = rowA & 7;
    int kpA = (l >> 4) & 1;
    int nB = wa * 32 + ((l & 16) >> 1) + (l & 7);
    uint32_t bRowBase = (uint32_t)nB * 128u;
    int bSwz = l & 7;
    int kpB = (l >> 3) & 1;

// load 8 raw A values of chunk (cc), unit (uu), into float dst[8]
#define LOADA8(dst, cc, uu) do {                                                \
    if ((cc) < 8) {                                                             \
        const float4* p_ = (const float4*)(aCvtBase + (cc) * KC2 + (uu) * 8);   \
        float4 v0_ = p_[0], v1_ = p_[1];                                        \
        dst[0]=v0_.x; dst[1]=v0_.y; dst[2]=v0_.z; dst[3]=v0_.w;                 \
        dst[4]=v1_.x; dst[5]=v1_.y; dst[6]=v1_.z; dst[7]=v1_.w;                 \
    } else {                                                                    \
        _Pragma("unroll")                                                       \
        for (int j_ = 0; j_ < 8; j_++) {                                        \
            int kk_ = chalf + (uu) * 8 + j_;                                    \
            float v_ = 0.f;                                                     \
            if (kk_ < KIM) {                                                    \
                int ci_ = (kk_ >= KW) ? 1 : 0;                                  \
                int kp_ = kk_ - ci_ * KW;                                       \
                int tg_ = tb + crow + kp_ - PADW;                               \
                if (tg_ >= 0 && tg_ < T_) v_ = awB[ci_ * T_ + tg_];             \
            }                                                                   \
            dst[j_] = v_;                                                       \
        }                                                                       \
    }                                                                           \
} while (0)

// convert 8 floats to bf16 hi/lo and store swizzled into buffer at hiBase
#define CVTSTORE(src, uu, hiBase) do {                                          \
    uint32_t hw_[4], lw_[4];                                                    \
    _Pragma("unroll")                                                           \
    for (int p_ = 0; p_ < 4; p_++) {                                            \
        float x0_ = src[2 * p_], x1_ = src[2 * p_ + 1];                         \
        uint32_t h_ = cvt_bf2(x1_, x0_);                                        \
        float f0_ = __uint_as_float(h_ << 16);                                  \
        float f1_ = __uint_as_float(h_ & 0xffff0000u);                          \
        lw_[p_] = cvt_bf2(x1_ - f1_, x0_ - f0_);                                \
        hw_[p_] = h_;                                                           \
    }                                                                           \
    int q_ = (chalf >> 3) + (uu);                                               \
    uint32_t off_ = cRowBase + (uint32_t)((q_ ^ cSwz) << 4);                    \
    *(uint4*)(smc + (hiBase) + off_) = make_uint4(hw_[0], hw_[1], hw_[2], hw_[3]); \
    *(uint4*)(smc + (hiBase) + 16384 + off_) = make_uint4(lw_[0], lw_[1], lw_[2], lw_[3]); \
} while (0)

// B copy for chunk (cc): 128 a-rows x 64 k, hi/lo, swizzled (L2-hot)
#define BCOPY(cc) do {                                                          \
    _Pragma("unroll")                                                           \
    for (int i_ = 0; i_ < 4; i_++) {                                            \
        int idx_ = i_ * 256 + tid;                                              \
        int n_ = idx_ >> 3, q_ = idx_ & 7;                                      \
        uint32_t off_ = (uint32_t)n_ * 128u + (uint32_t)(((q_ ^ (n_ & 7)) << 4)); \
        const char* sh_ = (const char*)g_Whi + (size_t)n_ * (KTOT * 2) + (cc) * 128 + q_ * 16; \
        const char* sl_ = (const char*)g_Wlo + (size_t)n_ * (KTOT * 2) + (cc) * 128 + q_ * 16; \
        *(uint4*)(smc + OFF_BHI + off_) = *(const uint4*)sh_;                   \
        *(uint4*)(smc + OFF_BLO + off_) = *(const uint4*)sl_;                   \
    }                                                                           \
} while (0)

    // ---- prologue: B(0) copy + direct convert A(0) into buf0 ----
    BCOPY(0);
    {
        float p0[8];
#pragma unroll
        for (int u = 0; u < 4; u++) {
            LOADA8(p0, 0, u);
            CVTSTORE(p0, u, OFF_A0H);
        }
    }
    __syncthreads();

#pragma unroll 1
    for (int c = 0; c < NCK; c++) {
        uint32_t curH = (c & 1) ? OFF_A1H : OFF_A0H;
        uint32_t nxtH = (c & 1) ? OFF_A0H : OFF_A1H;
        int doCvt = (c + 1 < NCK);

        float p0[8], p1[8];
        if (doCvt) LOADA8(p0, c + 1, 0);

        // ---- merged compute + interleaved convert of chunk c+1 ----
#pragma unroll
        for (int s = 0; s < 4; s++) {
            if (doCvt && s < 3) LOADA8(p1, c + 1, s + 1);
            uint32_t bh[8], bl[8];
            uint32_t kbB = (uint32_t)((((2 * s + kpB) ^ bSwz) << 4));
            ldsm4(sb + OFF_BHI + bRowBase + kbB,          bh[0], bh[1], bh[2], bh[3]);
            ldsm4(sb + OFF_BHI + bRowBase + 2048u + kbB,  bh[4], bh[5], bh[6], bh[7]);
            ldsm4(sb + OFF_BLO + bRowBase + kbB,          bl[0], bl[1], bl[2], bl[3]);
            ldsm4(sb + OFF_BLO + bRowBase + 2048u + kbB,  bl[4], bl[5], bl[6], bl[7]);
            uint32_t kbA = (uint32_t)((((2 * s + kpA) ^ aSwz) << 4));
#pragma unroll
            for (int mi = 0; mi < 4; mi++) {
                uint32_t ah[4], al[4];
                ldsm4(sb + curH + aRowBase + mi * 2048u + kbA, ah[0], ah[1], ah[2], ah[3]);
                ldsm4(sb + curH + 16384u + aRowBase + mi * 2048u + kbA, al[0], al[1], al[2], al[3]);
                mma16816(acc[mi][0], ah, bh[0], bh[1]);
                mma16816(acc[mi][1], ah, bh[2], bh[3]);
                mma16816(acc[mi][2], ah, bh[4], bh[5]);
                mma16816(acc[mi][3], ah, bh[6], bh[7]);
                mma16816(acc[mi][0], ah, bl[0], bl[1]);
                mma16816(acc[mi][1], ah, bl[2], bl[3]);
                mma16816(acc[mi][2], ah, bl[4], bl[5]);
                mma16816(acc[mi][3], ah, bl[6], bl[7]);
                mma16816(acc[mi][0], al, bh[0], bh[1]);
                mma16816(acc[mi][1], al, bh[2], bh[3]);
                mma16816(acc[mi][2], al, bh[4], bh[5]);
                mma16816(acc[mi][3], al, bh[6], bh[7]);
            }
            if (doCvt) {
                CVTSTORE(p0, s, nxtH);
                if (s < 3) {
#pragma unroll
                    for (int j = 0; j < 8; j++) p0[j] = p1[j];
                }
            }
        }
        __syncthreads();   // A(c+1) tile complete; compute(c) done
        if (doCvt) {
            BCOPY(c + 1);
            __syncthreads();
        }
    }
#undef LOADA8
#undef CVTSTORE
#undef BCOPY

    // ---- epilogue: en[t] = sum_a v[a] * tanh(D[t,a] + pq[a]) ----
    {
        const float* sPQ = (const float*)(smc + OFF_PQ);
        const float* sV  = (const float*)(smc + OFF_V);
        float* sEn = (float*)(smc + OFF_EN);   // [4 wa][128 t]
#pragma unroll
        for (int mi = 0; mi < 4; mi++) {
            float en1 = 0.f, en2 = 0.f;
#pragma unroll
            for (int nj = 0; nj < 4; nj++) {
                int a0 = wa * 32 + nj * 8 + 2 * (l & 3);
                float v0 = sV[a0], v1 = sV[a0 + 1];
                float q0 = sPQ[a0], q1 = sPQ[a0 + 1];
                en1 += v0 * tanh_fast(acc[mi][nj][0] + q0) + v1 * tanh_fast(acc[mi][nj][1] + q1);
                en2 += v0 * tanh_fast(acc[mi][nj][2] + q0) + v1 * tanh_fast(acc[mi][nj][3] + q1);
            }
            en1 += __shfl_xor_sync(0xffffffffu, en1, 1);
            en1 += __shfl_xor_sync(0xffffffffu, en1, 2);
            en2 += __shfl_xor_sync(0xffffffffu, en2, 1);
            en2 += __shfl_xor_sync(0xffffffffu, en2, 2);
            if ((l & 3) == 0) {
                int r1 = wt * 64 + mi * 16 + (l >> 2);
                sEn[wa * TM + r1] = en1;
                sEn[wa * TM + r1 + 8] = en2;
            }
        }
    }
    __syncthreads();
    if (tid < TM) {
        float* sEn = (float*)(smc + OFF_EN);
        float al = sEn[tid] + sEn[TM + tid] + sEn[2 * TM + tid] + sEn[3 * TM + tid] + vb[0];
        if (mask[b * T_ + tb + tid]) al += -1e25f;
        g_align[b * T_ + tb + tid] = al;
        ((float*)(smc + OFF_AL))[tid] = al;
    }
    __syncthreads();

    // ---- fused output GEMV partials: part[e] = sum_t align[t] * mem[b,tb+t,e] ----
    {
        const float* sAl = (const float*)(smc + OFF_AL);
        int e2 = tid * 2;
        float a0 = 0.f, a1 = 0.f;
        const float* mp = memB + e2;
#pragma unroll 8
        for (int t = 0; t < TM; t++) {
            float al = sAl[t];
            float2 m = *(const float2*)(mp + (size_t)t * E_);
            a0 = fmaf(al, m.x, a0);
            a1 = fmaf(al, m.y, a1);
        }
        float2 res; res.x = a0; res.y = a1;
        *(float2*)(g_part + (size_t)blockIdx.x * (B_ * E_) + b * E_ + e2) = res;
    }
}

// ---------------- softmax over T per batch -> attention_weights ----------------
__global__ void k_softmax(float* __restrict__ outw) {
    __shared__ float sE[T_];
    __shared__ float red[256];
    int b = blockIdx.x, tid = threadIdx.x;
    float mx = -3.4e38f;
    for (int i = tid; i < T_; i += 256) {
        float v = g_align[b * T_ + i];
        sE[i] = v;
        mx = fmaxf(mx, v);
    }
    red[tid] = mx;
    __syncthreads();
    for (int s = 128; s > 0; s >>= 1) {
        if (tid < s) red[tid] = fmaxf(red[tid], red[tid + s]);
        __syncthreads();
    }
    mx = red[0];
    __syncthreads();
    float sum = 0.f;
    for (int i = tid; i < T_; i += 256) {
        float ev = expf(sE[i] - mx);
        sE[i] = ev;
        sum += ev;
    }
    red[tid] = sum;
    __syncthreads();
    for (int s = 128; s > 0; s >>= 1) {
        if (tid < s) red[tid] += red[tid + s];
        __syncthreads();
    }
    float inv = 1.f / red[0];
    for (int i = tid; i < T_; i += 256) outw[b * T_ + i] = sE[i] * inv;
}

// ---------------- reduce GEMV partials ----------------
__global__ void k_reduce(float* __restrict__ outa) {
    int b = blockIdx.x, e = threadIdx.x;
    float s = 0.f;
#pragma unroll
    for (int p = 0; p < NPART; p++) s += g_part[(size_t)p * (B_ * E_) + b * E_ + e];
    outa[b * E_ + e] = s;
}

// ---------------- launch ----------------
extern "C" void kernel_launch(void* const* d_in, const int* in_sizes, int n_in,
                              void* d_out, int out_size) {
    (void)in_sizes; (void)n_in; (void)out_size;
    const float* hid  = (const float*)d_in[0];  // (B, R)
    const float* mem  = (const float*)d_in[1];  // (B, T, E)
    const float* aw   = (const float*)d_in[2];  // (B, 2, T)
    const int*   mask = (const int*)d_in[3];    // (B, T)
    const float* Wq   = (const float*)d_in[4];  // (R, A)
    const float* Wm   = (const float*)d_in[5];  // (E, A)
    const float* cw   = (const float*)d_in[6];  // (F, 2, K)
    const float* Wl   = (const float*)d_in[7];  // (F, A)
    const float* vw   = (const float*)d_in[8];  // (A,)
    const float* vb   = (const float*)d_in[9];  // (1,)

    float* out      = (float*)d_out;
    float* out_attn = out;              // (B, E)
    float* out_w    = out + B_ * E_;    // (B, T)

    static int configured = 0;
    if (!configured) {
        cudaFuncSetAttribute(k_main, cudaFuncAttributeMaxDynamicSharedMemorySize, SMEM_SZ);
        configured = 1;
    }

    k_pq<<<B_, 128>>>(hid, Wq);
    k_wcat<<<KTOT, 128>>>(Wm, cw, Wl);
    dim3 gm(T_ / TM, B_);
    k_main<<<gm, 256, SMEM_SZ>>>(mem, aw, mask, vw, vb);
    k_softmax<<<B_, 256>>>(out_w);
    k_reduce<<<B_, E_>>>(out_attn);
}